// round 10
// baseline (speedup 1.0000x reference)
#include <cuda_runtime.h>
#include <cooperative_groups.h>
namespace cg = cooperative_groups;

#define TSTEPS 512
#define BATCH  256
#define ISZ    64
#define HSZ    256
#define BCTA   4
#define JHALF  128
#define NTH    512
#define KC     16                 // warps
#define KH_H   8                  // h-rows per warp per half
#define KX_W   (ISZ / KC)         // 4 x-rows per warp
#define NBLOCKS ((BATCH / BCTA) * 2)   // 128

__device__ float g_WT[(HSZ + ISZ) * HSZ];   // rows 0..255 = W_hh^T, 256..319 = W_ih^T
__device__ float g_bias[HSZ];

__global__ void prep_kernel(const float* __restrict__ W_ih,
                            const float* __restrict__ W_hh,
                            const float* __restrict__ b_ih,
                            const float* __restrict__ b_hh) {
    int idx = blockIdx.x * blockDim.x + threadIdx.x;
    int stride = gridDim.x * blockDim.x;
    for (int p = idx; p < (HSZ + ISZ) * HSZ; p += stride) {
        int i = p >> 8, j = p & 255;
        g_WT[p] = (i < HSZ) ? W_hh[j * HSZ + i] : W_ih[j * ISZ + (i - HSZ)];
    }
    if (idx < HSZ) g_bias[idx] = b_ih[idx] + b_hh[idx];
}

// SMEM byte offsets
#define S_OFF    0          // h state, dup'd: 2 bufs x 256 rows x 4 u64  = 16384 B
#define X_OFF    16384      // x stage, dup'd: 2 bufs x 64 rows x 4 u64   =  4096 B
#define RED_OFF  20480      // partials: padded, 16*272 u64               = 34816 B
#define SMEM_BYTES 55296
#define SBUF_B   8192
#define XBUF_B   2048
#define REDK     272        // u64 stride per k-chunk (=544 floats)
#define REDB     68         // u64 stride per batch   (=136 floats)

#define FMA2(d, a, b) asm volatile("fma.rn.f32x2 %0, %1, %2, %0;" : "+l"(d) : "l"(a), "l"(b))

static __device__ __forceinline__ unsigned s2u(const void* p) {
    return (unsigned)__cvta_generic_to_shared(p);
}
static __device__ __forceinline__ unsigned long long dup2(float v) {
    unsigned long long d;
    asm("mov.b64 %0, {%1, %1};" : "=l"(d) : "f"(v));
    return d;
}
static __device__ __forceinline__ float tanh_fast(float v) {
    float e, r;
    asm("ex2.approx.f32 %0, %1;" : "=f"(e) : "f"(v * 2.885390082f));
    asm("rcp.approx.f32 %0, %1;" : "=f"(r) : "f"(e + 1.0f));
    return 1.0f - 2.0f * r;
}
static __device__ __forceinline__ void lds_v2u64(unsigned long long& a, unsigned long long& b, unsigned ad) {
    asm volatile("ld.shared.v2.u64 {%0,%1}, [%2];" : "=l"(a), "=l"(b) : "r"(ad));
}
static __device__ __forceinline__ void sts_u64(unsigned ad, unsigned long long v) {
    asm volatile("st.shared.u64 [%0], %1;" :: "r"(ad), "l"(v) : "memory");
}
static __device__ __forceinline__ void sts_cluster_u64(unsigned ad, unsigned long long v) {
    asm volatile("st.shared::cluster.u64 [%0], %1;" :: "r"(ad), "l"(v) : "memory");
}
static __device__ __forceinline__ float lds_f32(unsigned ad) {
    float v;
    asm volatile("ld.shared.f32 %0, [%1];" : "=f"(v) : "r"(ad));
    return v;
}
static __device__ __forceinline__ void bar_arrive_local(unsigned bar) {
    asm volatile("mbarrier.arrive.release.cta.shared::cta.b64 _, [%0];" :: "r"(bar) : "memory");
}
static __device__ __forceinline__ void bar_arrive_remote(unsigned bar_remote) {
    asm volatile("mbarrier.arrive.release.cluster.shared::cluster.b64 _, [%0];" :: "r"(bar_remote) : "memory");
}
static __device__ __forceinline__ void bar_wait(unsigned bar, unsigned phase) {
    asm volatile("{\n\t.reg .pred P;\n\t"
                 "WLOOP_%=:\n\t"
                 "mbarrier.try_wait.parity.acquire.cluster.shared::cta.b64 P, [%0], %1, 0x989680;\n\t"
                 "@P bra.uni WDONE_%=;\n\t"
                 "bra.uni WLOOP_%=;\n\t"
                 "WDONE_%=:\n\t}"
                 :: "r"(bar), "r"(phase) : "memory");
}
static __device__ __forceinline__ unsigned mapa_u32(unsigned ad, int peer) {
    unsigned r;
    asm("mapa.shared::cluster.u32 %0, %1, %2;" : "=r"(r) : "r"(ad), "r"(peer));
    return r;
}
static __device__ __forceinline__ unsigned long long ldg_u64(const float* p) {
    unsigned long long v;
    asm volatile("ld.global.nc.u64 %0, [%1];" : "=l"(v) : "l"(p));
    return v;
}

// 8-row GEMM half with explicit double-buffered state loads
#define GEMM_HALF(W0, W1, sadr)                                                  \
    {                                                                            \
        unsigned long long c0x, c0y, c0z, c0w, n0x, n0y, n0z, n0w;               \
        lds_v2u64(c0x, c0y, (sadr));                                             \
        lds_v2u64(c0z, c0w, (sadr) + 16);                                        \
        _Pragma("unroll")                                                        \
        for (int ii = 0; ii < KH_H; ++ii) {                                      \
            if (ii + 1 < KH_H) {                                                 \
                lds_v2u64(n0x, n0y, (sadr) + (ii + 1) * 32);                     \
                lds_v2u64(n0z, n0w, (sadr) + (ii + 1) * 32 + 16);                \
            }                                                                    \
            FMA2(a0, W0[ii], c0x);  FMA2(a1, W1[ii], c0x);                       \
            FMA2(a2, W0[ii], c0y);  FMA2(a3, W1[ii], c0y);                       \
            FMA2(a4, W0[ii], c0z);  FMA2(a5, W1[ii], c0z);                       \
            FMA2(a6, W0[ii], c0w);  FMA2(a7, W1[ii], c0w);                       \
            c0x = n0x; c0y = n0y; c0z = n0z; c0w = n0w;                          \
        }                                                                        \
    }

__global__ void __cluster_dims__(2, 1, 1) __launch_bounds__(NTH, 1)
rnn_kernel(const float* __restrict__ x,
           const float* __restrict__ fc_W,
           const float* __restrict__ fc_b,
           float* __restrict__ out) {
    extern __shared__ float smdyn[];
    __shared__ __align__(8) unsigned long long barrier_s;

    cg::cluster_group cl = cg::this_cluster();
    const int rank = (int)cl.block_rank();
    const int tid  = threadIdx.x;
    const int lane = tid & 31;
    const int kc   = tid >> 5;
    const int b0   = (blockIdx.x >> 1) * BCTA;
    const int peer = rank ^ 1;

    const unsigned smbase = s2u(smdyn);
    const unsigned Sb   = smbase + S_OFF;
    const unsigned Xb   = smbase + X_OFF;
    const unsigned REDb = smbase + RED_OFF;
    const unsigned barA = s2u(&barrier_s);

    // ---- h weights -> regs (local-origin + peer-origin halves); x weights via LDG
    unsigned long long wL0[KH_H], wL1[KH_H], wP0[KH_H], wP1[KH_H];
    const int cb = rank * JHALF + 2 * lane;
    {
        #pragma unroll
        for (int ii = 0; ii < KH_H; ++ii) {
            int iL = rank * JHALF + kc * KH_H + ii;
            int iP = peer * JHALF + kc * KH_H + ii;
            wL0[ii] = *reinterpret_cast<const unsigned long long*>(&g_WT[iL * HSZ + cb]);
            wL1[ii] = *reinterpret_cast<const unsigned long long*>(&g_WT[iL * HSZ + cb + 64]);
            wP0[ii] = *reinterpret_cast<const unsigned long long*>(&g_WT[iP * HSZ + cb]);
            wP1[ii] = *reinterpret_cast<const unsigned long long*>(&g_WT[iP * HSZ + cb + 64]);
        }
    }
    const float* wxg = &g_WT[(HSZ + kc * KX_W) * HSZ + cb];   // x-weight base (LDG per step)
    const float breg = g_bias[rank * JHALF + (tid >> 2)];

    // ---- init: both h bufs = 0; stage x(0)->Xs[0], x(1)->Xs[1]
    for (int p = tid; p < 2 * HSZ * BCTA * 2; p += NTH) smdyn[p] = 0.f;
    const float* xb = x + (size_t)b0 * TSTEPS * ISZ;
    if (tid < ISZ * BCTA) {
        int b = tid >> 6, i = tid & 63;
        sts_u64(Xb + (unsigned)(i * 4 + b) * 8,          dup2(xb[(size_t)b * TSTEPS * ISZ + i]));
        sts_u64(Xb + XBUF_B + (unsigned)(i * 4 + b) * 8, dup2(xb[(size_t)b * TSTEPS * ISZ + ISZ + i]));
    }
    if (tid == 0)
        asm volatile("mbarrier.init.shared.b64 [%0], 2;" :: "r"(barA) : "memory");
    __syncthreads();
    asm volatile("barrier.cluster.arrive.aligned;" ::: "memory");
    asm volatile("barrier.cluster.wait.aligned;" ::: "memory");

    const unsigned peerSb  = mapa_u32(Sb, peer);
    const unsigned peerBar = mapa_u32(barA, peer);

    // bootstrap arrivals so first bar_wait passes (R7-proven: tid0, count 2)
    if (tid == 0) { bar_arrive_local(barA); bar_arrive_remote(peerBar); }

    // ---- acc = x-part(0)
    unsigned long long a0 = 0, a1 = 0, a2 = 0, a3 = 0, a4 = 0, a5 = 0, a6 = 0, a7 = 0;
    {
        unsigned xadr = Xb + (unsigned)(kc * KX_W) * 32;
        #pragma unroll
        for (int ii = 0; ii < KX_W; ++ii) {
            unsigned long long wx0 = ldg_u64(wxg + ii * HSZ);
            unsigned long long wx1 = ldg_u64(wxg + ii * HSZ + 64);
            unsigned long long hx, hy, hz, hw;
            lds_v2u64(hx, hy, xadr + ii * 32);
            lds_v2u64(hz, hw, xadr + ii * 32 + 16);
            FMA2(a0, wx0, hx);  FMA2(a1, wx1, hx);
            FMA2(a2, wx0, hy);  FMA2(a3, wx1, hy);
            FMA2(a4, wx0, hz);  FMA2(a5, wx1, hz);
            FMA2(a6, wx0, hw);  FMA2(a7, wx1, hw);
        }
    }

    int cur = 0;
    unsigned phase = 0;
    const int rj = tid >> 2, rb = tid & 3;
    const unsigned pubIdx = (unsigned)((rank * JHALF + rj) * 4 + rb) * 8;
    const unsigned redLd  = REDb + (unsigned)(rb * 136 + rj) * 4;
    const unsigned redSt  = REDb + (unsigned)(kc * REDK + lane) * 8;
    const unsigned adrL   = Sb + (unsigned)((rank * JHALF + kc * KH_H) * 4) * 8;
    const unsigned adrP   = Sb + (unsigned)((peer * JHALF + kc * KH_H) * 4) * 8;

    for (int t = 0; t < TSTEPS; ++t) {
        // prefetch x(t+2)
        float xv = 0.f;
        if (tid < ISZ * BCTA && t + 2 < TSTEPS)
            xv = xb[(size_t)(tid >> 6) * TSTEPS * ISZ + (size_t)(t + 2) * ISZ + (tid & 63)];

        // ---- local-origin half of h-GEMM
        GEMM_HALF(wL0, wL1, adrL + cur * SBUF_B)

        // ---- wait for peer's pushed half
        bar_wait(barA, phase);
        phase ^= 1;

        // ---- peer-origin half of h-GEMM
        GEMM_HALF(wP0, wP1, adrP + cur * SBUF_B)

        // ---- partials
        sts_u64(redSt,                 a0);  sts_u64(redSt + 32 * 8,              a1);
        sts_u64(redSt + REDB * 8,      a2);  sts_u64(redSt + (REDB + 32) * 8,     a3);
        sts_u64(redSt + 2 * REDB * 8,  a4);  sts_u64(redSt + (2 * REDB + 32) * 8, a5);
        sts_u64(redSt + 3 * REDB * 8,  a6);  sts_u64(redSt + (3 * REDB + 32) * 8, a7);
        __syncthreads();

        // ---- reduce + tanh + publish local & DSMEM
        {
            float s0 = breg, s1 = 0.f, s2 = 0.f, s3 = 0.f;
            #pragma unroll
            for (int k = 0; k < KC; k += 4) {
                s0 += lds_f32(redLd + (k + 0) * 544 * 4);
                s1 += lds_f32(redLd + (k + 1) * 544 * 4);
                s2 += lds_f32(redLd + (k + 2) * 544 * 4);
                s3 += lds_f32(redLd + (k + 3) * 544 * 4);
            }
            unsigned long long hd = dup2(tanh_fast((s0 + s1) + (s2 + s3)));
            unsigned dst = (cur ^ 1) * SBUF_B + pubIdx;
            sts_u64(Sb + dst, hd);
            sts_cluster_u64(peerSb + dst, hd);
        }
        // stage x(t+2)
        if (tid < ISZ * BCTA && t + 2 < TSTEPS) {
            int b = tid >> 6, i = tid & 63;
            sts_u64(Xb + (t & 1) * XBUF_B + (unsigned)(i * 4 + b) * 8, dup2(xv));
        }
        __syncthreads();
        if (tid == 0) { bar_arrive_local(barA); bar_arrive_remote(peerBar); }

        // ---- x-part(t+1): overlaps peer round trip
        a0 = a1 = a2 = a3 = a4 = a5 = a6 = a7 = 0;
        if (t + 1 < TSTEPS) {
            unsigned xadr = Xb + ((t + 1) & 1) * XBUF_B + (unsigned)(kc * KX_W) * 32;
            #pragma unroll
            for (int ii = 0; ii < KX_W; ++ii) {
                unsigned long long wx0 = ldg_u64(wxg + ii * HSZ);
                unsigned long long wx1 = ldg_u64(wxg + ii * HSZ + 64);
                unsigned long long hx, hy, hz, hw;
                lds_v2u64(hx, hy, xadr + ii * 32);
                lds_v2u64(hz, hw, xadr + ii * 32 + 16);
                FMA2(a0, wx0, hx);  FMA2(a1, wx1, hx);
                FMA2(a2, wx0, hy);  FMA2(a3, wx1, hy);
                FMA2(a4, wx0, hz);  FMA2(a5, wx1, hz);
                FMA2(a6, wx0, hw);  FMA2(a7, wx1, hw);
            }
        }
        cur ^= 1;
    }

    // peer's final DSMEM push must land before rank0 reads full state
    asm volatile("barrier.cluster.arrive.aligned;" ::: "memory");
    asm volatile("barrier.cluster.wait.aligned;" ::: "memory");

    // ---- final FC (O=1), rank 0 only
    if (rank == 0) {
        const float* scur = smdyn + cur * (SBUF_B / 4);
        float* redf = smdyn + RED_OFF / 4;
        if (tid < HSZ) {
            float fw = fc_W[tid];
            float p0 = scur[tid * 8 + 0] * fw;
            float p1 = scur[tid * 8 + 2] * fw;
            float p2 = scur[tid * 8 + 4] * fw;
            float p3 = scur[tid * 8 + 6] * fw;
            #pragma unroll
            for (int off = 16; off; off >>= 1) {
                p0 += __shfl_down_sync(0xffffffffu, p0, off);
                p1 += __shfl_down_sync(0xffffffffu, p1, off);
                p2 += __shfl_down_sync(0xffffffffu, p2, off);
                p3 += __shfl_down_sync(0xffffffffu, p3, off);
            }
            if (lane == 0) {
                redf[kc * 4 + 0] = p0; redf[kc * 4 + 1] = p1;
                redf[kc * 4 + 2] = p2; redf[kc * 4 + 3] = p3;
            }
        }
        __syncthreads();
        if (tid < 4) {
            float v = fc_b[0];
            #pragma unroll
            for (int k = 0; k < 8; ++k) v += redf[k * 4 + tid];
            out[b0 + tid] = v;
        }
    }
}

extern "C" void kernel_launch(void* const* d_in, const int* in_sizes, int n_in,
                              void* d_out, int out_size) {
    const float* x    = (const float*)d_in[0];
    const float* W_ih = (const float*)d_in[1];
    const float* W_hh = (const float*)d_in[2];
    const float* b_ih = (const float*)d_in[3];
    const float* b_hh = (const float*)d_in[4];
    const float* fc_W = (const float*)d_in[5];
    const float* fc_b = (const float*)d_in[6];
    float* out = (float*)d_out;

    cudaFuncSetAttribute(rnn_kernel, cudaFuncAttributeMaxDynamicSharedMemorySize, SMEM_BYTES);

    prep_kernel<<<128, 256>>>(W_ih, W_hh, b_ih, b_hh);
    rnn_kernel<<<NBLOCKS, NTH, SMEM_BYTES>>>(x, fc_W, fc_b, out);
}

// round 11
// speedup vs baseline: 1.1378x; 1.1378x over previous
#include <cuda_runtime.h>
#include <cooperative_groups.h>
namespace cg = cooperative_groups;

#define TSTEPS 512
#define BATCH  256
#define ISZ    64
#define HSZ    256
#define BCTA   4
#define JHALF  128
#define NTH    512
#define KC     16                 // warps
#define KH_H   8                  // h-rows per warp per half
#define KX_W   (ISZ / KC)         // 4 x-rows per warp
#define NBLOCKS ((BATCH / BCTA) * 2)   // 128

__device__ float g_WT[(HSZ + ISZ) * HSZ];   // rows 0..255 = W_hh^T, 256..319 = W_ih^T
__device__ float g_bias[HSZ];

__global__ void prep_kernel(const float* __restrict__ W_ih,
                            const float* __restrict__ W_hh,
                            const float* __restrict__ b_ih,
                            const float* __restrict__ b_hh) {
    int idx = blockIdx.x * blockDim.x + threadIdx.x;
    int stride = gridDim.x * blockDim.x;
    for (int p = idx; p < (HSZ + ISZ) * HSZ; p += stride) {
        int i = p >> 8, j = p & 255;
        g_WT[p] = (i < HSZ) ? W_hh[j * HSZ + i] : W_ih[j * ISZ + (i - HSZ)];
    }
    if (idx < HSZ) g_bias[idx] = b_ih[idx] + b_hh[idx];
}

// SMEM byte offsets
#define S_OFF    0          // h state, dup'd: 2 bufs x 256 rows x 4 u64  = 16384 B
#define X_OFF    16384      // x stage, dup'd: 2 bufs x 64 rows x 4 u64   =  4096 B
#define RED_OFF  20480      // partials: padded, 16*272 u64               = 34816 B
#define SMEM_BYTES 55296
#define SBUF_B   8192
#define XBUF_B   2048
#define REDK     272        // u64 stride per k-chunk (=544 floats)
#define REDB     68         // u64 stride per batch   (=136 floats)

#define FMA2(d, a, b) asm volatile("fma.rn.f32x2 %0, %1, %2, %0;" : "+l"(d) : "l"(a), "l"(b))

static __device__ __forceinline__ unsigned s2u(const void* p) {
    return (unsigned)__cvta_generic_to_shared(p);
}
static __device__ __forceinline__ unsigned long long dup2(float v) {
    unsigned long long d;
    asm("mov.b64 %0, {%1, %1};" : "=l"(d) : "f"(v));
    return d;
}
static __device__ __forceinline__ float tanh_fast(float v) {
    float e, r;
    asm("ex2.approx.f32 %0, %1;" : "=f"(e) : "f"(v * 2.885390082f));
    asm("rcp.approx.f32 %0, %1;" : "=f"(r) : "f"(e + 1.0f));
    return 1.0f - 2.0f * r;
}
static __device__ __forceinline__ void lds_v2u64(unsigned long long& a, unsigned long long& b, unsigned ad) {
    asm volatile("ld.shared.v2.u64 {%0,%1}, [%2];" : "=l"(a), "=l"(b) : "r"(ad));
}
static __device__ __forceinline__ void sts_u64(unsigned ad, unsigned long long v) {
    asm volatile("st.shared.u64 [%0], %1;" :: "r"(ad), "l"(v) : "memory");
}
static __device__ __forceinline__ void sts_cluster_u64(unsigned ad, unsigned long long v) {
    asm volatile("st.shared::cluster.u64 [%0], %1;" :: "r"(ad), "l"(v) : "memory");
}
static __device__ __forceinline__ float lds_f32(unsigned ad) {
    float v;
    asm volatile("ld.shared.f32 %0, [%1];" : "=f"(v) : "r"(ad));
    return v;
}
static __device__ __forceinline__ void bar_arrive_remote(unsigned bar_remote) {
    asm volatile("mbarrier.arrive.release.cluster.shared::cluster.b64 _, [%0];" :: "r"(bar_remote) : "memory");
}
static __device__ __forceinline__ void bar_wait(unsigned bar, unsigned phase) {
    asm volatile("{\n\t.reg .pred P;\n\t"
                 "WLOOP_%=:\n\t"
                 "mbarrier.try_wait.parity.acquire.cluster.shared::cta.b64 P, [%0], %1, 0x989680;\n\t"
                 "@P bra.uni WDONE_%=;\n\t"
                 "bra.uni WLOOP_%=;\n\t"
                 "WDONE_%=:\n\t}"
                 :: "r"(bar), "r"(phase) : "memory");
}
static __device__ __forceinline__ unsigned mapa_u32(unsigned ad, int peer) {
    unsigned r;
    asm("mapa.shared::cluster.u32 %0, %1, %2;" : "=r"(r) : "r"(ad), "r"(peer));
    return r;
}

__global__ void __cluster_dims__(2, 1, 1) __launch_bounds__(NTH, 1)
rnn_kernel(const float* __restrict__ x,
           const float* __restrict__ fc_W,
           const float* __restrict__ fc_b,
           float* __restrict__ out) {
    extern __shared__ float smdyn[];
    __shared__ __align__(8) unsigned long long barrier_s;

    cg::cluster_group cl = cg::this_cluster();
    const int rank = (int)cl.block_rank();
    const int tid  = threadIdx.x;
    const int lane = tid & 31;
    const int kc   = tid >> 5;
    const int b0   = (blockIdx.x >> 1) * BCTA;
    const int peer = rank ^ 1;

    const unsigned smbase = s2u(smdyn);
    const unsigned Sb   = smbase + S_OFF;
    const unsigned Xb   = smbase + X_OFF;
    const unsigned REDb = smbase + RED_OFF;
    const unsigned barA = s2u(&barrier_s);

    // ---- weights -> regs: 8 local-origin rows, 8 peer-origin rows, 4 x-rows
    unsigned long long wL0[KH_H], wL1[KH_H], wP0[KH_H], wP1[KH_H], wx0[KX_W], wx1[KX_W];
    {
        const int cb = rank * JHALF + 2 * lane;
        #pragma unroll
        for (int ii = 0; ii < KH_H; ++ii) {
            int iL = rank * JHALF + kc * KH_H + ii;
            int iP = peer * JHALF + kc * KH_H + ii;
            wL0[ii] = *reinterpret_cast<const unsigned long long*>(&g_WT[iL * HSZ + cb]);
            wL1[ii] = *reinterpret_cast<const unsigned long long*>(&g_WT[iL * HSZ + cb + 64]);
            wP0[ii] = *reinterpret_cast<const unsigned long long*>(&g_WT[iP * HSZ + cb]);
            wP1[ii] = *reinterpret_cast<const unsigned long long*>(&g_WT[iP * HSZ + cb + 64]);
        }
        #pragma unroll
        for (int ii = 0; ii < KX_W; ++ii) {
            int i = HSZ + kc * KX_W + ii;
            wx0[ii] = *reinterpret_cast<const unsigned long long*>(&g_WT[i * HSZ + cb]);
            wx1[ii] = *reinterpret_cast<const unsigned long long*>(&g_WT[i * HSZ + cb + 64]);
        }
    }
    const float breg = g_bias[rank * JHALF + (tid >> 2)];

    // ---- init: both h bufs = 0; stage x(0)->Xs[0], x(1)->Xs[1]
    for (int p = tid; p < 2 * HSZ * BCTA * 2; p += NTH) smdyn[p] = 0.f;
    const float* xb = x + (size_t)b0 * TSTEPS * ISZ;
    if (tid < ISZ * BCTA) {
        int b = tid >> 6, i = tid & 63;
        sts_u64(Xb + (unsigned)(i * 4 + b) * 8,          dup2(xb[(size_t)b * TSTEPS * ISZ + i]));
        sts_u64(Xb + XBUF_B + (unsigned)(i * 4 + b) * 8, dup2(xb[(size_t)b * TSTEPS * ISZ + ISZ + i]));
    }
    if (tid == 0)
        asm volatile("mbarrier.init.shared.b64 [%0], 1;" :: "r"(barA) : "memory");
    __syncthreads();
    asm volatile("barrier.cluster.arrive.aligned;" ::: "memory");
    asm volatile("barrier.cluster.wait.aligned;" ::: "memory");

    const unsigned peerSb  = mapa_u32(Sb, peer);
    const unsigned peerBar = mapa_u32(barA, peer);

    // bootstrap: arm peer's barrier so its first wait passes
    if (tid == 0) bar_arrive_remote(peerBar);

    // ---- acc = x-part(0)
    unsigned long long a0 = 0, a1 = 0, a2 = 0, a3 = 0, a4 = 0, a5 = 0, a6 = 0, a7 = 0;
    {
        unsigned xadr = Xb + (unsigned)(kc * KX_W) * 32;
        #pragma unroll
        for (int ii = 0; ii < KX_W; ++ii) {
            unsigned long long hx, hy, hz, hw;
            lds_v2u64(hx, hy, xadr + ii * 32);
            lds_v2u64(hz, hw, xadr + ii * 32 + 16);
            FMA2(a0, wx0[ii], hx);  FMA2(a1, wx1[ii], hx);
            FMA2(a2, wx0[ii], hy);  FMA2(a3, wx1[ii], hy);
            FMA2(a4, wx0[ii], hz);  FMA2(a5, wx1[ii], hz);
            FMA2(a6, wx0[ii], hw);  FMA2(a7, wx1[ii], hw);
        }
    }

    int cur = 0;
    unsigned phase = 0;
    const int rj = tid >> 2, rb = tid & 3;
    const unsigned pubIdx = (unsigned)((rank * JHALF + rj) * 4 + rb) * 8;
    const unsigned redLd  = REDb + (unsigned)(rb * 136 + rj) * 4;
    const unsigned redSt  = REDb + (unsigned)(kc * REDK + lane) * 8;
    const unsigned adrL   = Sb + (unsigned)((rank * JHALF + kc * KH_H) * 4) * 8;
    const unsigned adrP   = Sb + (unsigned)((peer * JHALF + kc * KH_H) * 4) * 8;

    for (int t = 0; t < TSTEPS; ++t) {
        // prefetch x(t+2)
        float xv = 0.f;
        if (tid < ISZ * BCTA && t + 2 < TSTEPS)
            xv = xb[(size_t)(tid >> 6) * TSTEPS * ISZ + (size_t)(t + 2) * ISZ + (tid & 63)];

        // ---- local-origin half of h-GEMM (rows produced by THIS CTA)
        {
            unsigned sadr = adrL + cur * SBUF_B;
            #pragma unroll
            for (int ii = 0; ii < KH_H; ++ii) {
                unsigned long long hx, hy, hz, hw;
                lds_v2u64(hx, hy, sadr + ii * 32);
                lds_v2u64(hz, hw, sadr + ii * 32 + 16);
                FMA2(a0, wL0[ii], hx);  FMA2(a1, wL1[ii], hx);
                FMA2(a2, wL0[ii], hy);  FMA2(a3, wL1[ii], hy);
                FMA2(a4, wL0[ii], hz);  FMA2(a5, wL1[ii], hz);
                FMA2(a6, wL0[ii], hw);  FMA2(a7, wL1[ii], hw);
            }
        }

        // ---- wait for peer's pushed half
        bar_wait(barA, phase);
        phase ^= 1;

        // ---- peer-origin half of h-GEMM
        {
            unsigned sadr = adrP + cur * SBUF_B;
            #pragma unroll
            for (int ii = 0; ii < KH_H; ++ii) {
                unsigned long long hx, hy, hz, hw;
                lds_v2u64(hx, hy, sadr + ii * 32);
                lds_v2u64(hz, hw, sadr + ii * 32 + 16);
                FMA2(a0, wP0[ii], hx);  FMA2(a1, wP1[ii], hx);
                FMA2(a2, wP0[ii], hy);  FMA2(a3, wP1[ii], hy);
                FMA2(a4, wP0[ii], hz);  FMA2(a5, wP1[ii], hz);
                FMA2(a6, wP0[ii], hw);  FMA2(a7, wP1[ii], hw);
            }
        }

        // ---- partials
        sts_u64(redSt,                 a0);  sts_u64(redSt + 32 * 8,              a1);
        sts_u64(redSt + REDB * 8,      a2);  sts_u64(redSt + (REDB + 32) * 8,     a3);
        sts_u64(redSt + 2 * REDB * 8,  a4);  sts_u64(redSt + (2 * REDB + 32) * 8, a5);
        sts_u64(redSt + 3 * REDB * 8,  a6);  sts_u64(redSt + (3 * REDB + 32) * 8, a7);
        __syncthreads();

        // ---- x-part(t+1) FIRST (independent of the reduce -> overlaps its LDS latency)
        a0 = a1 = a2 = a3 = a4 = a5 = a6 = a7 = 0;
        if (t + 1 < TSTEPS) {
            unsigned xadr = Xb + ((t + 1) & 1) * XBUF_B + (unsigned)(kc * KX_W) * 32;
            #pragma unroll
            for (int ii = 0; ii < KX_W; ++ii) {
                unsigned long long hx, hy, hz, hw;
                lds_v2u64(hx, hy, xadr + ii * 32);
                lds_v2u64(hz, hw, xadr + ii * 32 + 16);
                FMA2(a0, wx0[ii], hx);  FMA2(a1, wx1[ii], hx);
                FMA2(a2, wx0[ii], hy);  FMA2(a3, wx1[ii], hy);
                FMA2(a4, wx0[ii], hz);  FMA2(a5, wx1[ii], hz);
                FMA2(a6, wx0[ii], hw);  FMA2(a7, wx1[ii], hw);
            }
        }

        // ---- reduce + tanh + publish local & DSMEM
        {
            float s0 = breg, s1 = 0.f, s2 = 0.f, s3 = 0.f;
            #pragma unroll
            for (int k = 0; k < KC; k += 4) {
                s0 += lds_f32(redLd + (k + 0) * 544 * 4);
                s1 += lds_f32(redLd + (k + 1) * 544 * 4);
                s2 += lds_f32(redLd + (k + 2) * 544 * 4);
                s3 += lds_f32(redLd + (k + 3) * 544 * 4);
            }
            unsigned long long hd = dup2(tanh_fast((s0 + s1) + (s2 + s3)));
            unsigned dst = (cur ^ 1) * SBUF_B + pubIdx;
            sts_u64(Sb + dst, hd);
            sts_cluster_u64(peerSb + dst, hd);
        }
        // stage x(t+2)
        if (tid < ISZ * BCTA && t + 2 < TSTEPS) {
            int b = tid >> 6, i = tid & 63;
            sts_u64(Xb + (t & 1) * XBUF_B + (unsigned)(i * 4 + b) * 8, dup2(xv));
        }
        __syncthreads();
        if (tid == 0) bar_arrive_remote(peerBar);
        cur ^= 1;
    }

    // peer's final DSMEM push must land before rank0 reads full state
    asm volatile("barrier.cluster.arrive.aligned;" ::: "memory");
    asm volatile("barrier.cluster.wait.aligned;" ::: "memory");

    // ---- final FC (O=1), rank 0 only
    if (rank == 0) {
        const float* scur = smdyn + cur * (SBUF_B / 4);
        float* redf = smdyn + RED_OFF / 4;
        if (tid < HSZ) {
            float fw = fc_W[tid];
            float p0 = scur[tid * 8 + 0] * fw;
            float p1 = scur[tid * 8 + 2] * fw;
            float p2 = scur[tid * 8 + 4] * fw;
            float p3 = scur[tid * 8 + 6] * fw;
            #pragma unroll
            for (int off = 16; off; off >>= 1) {
                p0 += __shfl_down_sync(0xffffffffu, p0, off);
                p1 += __shfl_down_sync(0xffffffffu, p1, off);
                p2 += __shfl_down_sync(0xffffffffu, p2, off);
                p3 += __shfl_down_sync(0xffffffffu, p3, off);
            }
            if (lane == 0) {
                redf[kc * 4 + 0] = p0; redf[kc * 4 + 1] = p1;
                redf[kc * 4 + 2] = p2; redf[kc * 4 + 3] = p3;
            }
        }
        __syncthreads();
        if (tid < 4) {
            float v = fc_b[0];
            #pragma unroll
            for (int k = 0; k < 8; ++k) v += redf[k * 4 + tid];
            out[b0 + tid] = v;
        }
    }
}

extern "C" void kernel_launch(void* const* d_in, const int* in_sizes, int n_in,
                              void* d_out, int out_size) {
    const float* x    = (const float*)d_in[0];
    const float* W_ih = (const float*)d_in[1];
    const float* W_hh = (const float*)d_in[2];
    const float* b_ih = (const float*)d_in[3];
    const float* b_hh = (const float*)d_in[4];
    const float* fc_W = (const float*)d_in[5];
    const float* fc_b = (const float*)d_in[6];
    float* out = (float*)d_out;

    cudaFuncSetAttribute(rnn_kernel, cudaFuncAttributeMaxDynamicSharedMemorySize, SMEM_BYTES);

    prep_kernel<<<128, 256>>>(W_ih, W_hh, b_ih, b_hh);
    rnn_kernel<<<NBLOCKS, NTH, SMEM_BYTES>>>(x, fc_W, fc_b, out);
}

// round 14
// speedup vs baseline: 1.2951x; 1.1383x over previous
#include <cuda_runtime.h>
#include <cuda_bf16.h>
#include <cooperative_groups.h>
namespace cg = cooperative_groups;

#define TSTEPS 512
#define ISZ    64
#define HSZ    256
#define NB     8              // batch per cluster = MMA N
#define NTH    512
#define NBLOCKS 64            // 32 clusters x 2 CTAs
#define KP     160            // u32 bf16-pairs per weight row (K=320)

__device__ unsigned g_W1[HSZ * KP];   // bf16-hi pairs, [j][kp], global k order (h 0..255, x 256..319)
__device__ unsigned g_W2[HSZ * KP];   // bf16-lo pairs
__device__ float    g_bias[HSZ];

__global__ void prep_kernel(const float* __restrict__ W_ih,
                            const float* __restrict__ W_hh,
                            const float* __restrict__ b_ih,
                            const float* __restrict__ b_hh) {
    int idx = blockIdx.x * blockDim.x + threadIdx.x;
    int stride = gridDim.x * blockDim.x;
    for (int p = idx; p < HSZ * KP; p += stride) {
        int j = p / KP, kp = p % KP;
        unsigned hi2 = 0, lo2 = 0;
        #pragma unroll
        for (int q = 0; q < 2; ++q) {
            int k = 2 * kp + q;
            float w = (k < HSZ) ? W_hh[j * HSZ + k] : W_ih[j * ISZ + (k - HSZ)];
            unsigned short h = __bfloat16_as_ushort(__float2bfloat16(w));
            float r = w - __bfloat162float(__ushort_as_bfloat16(h));
            unsigned short l = __bfloat16_as_ushort(__float2bfloat16(r));
            hi2 |= (unsigned)h << (16 * q);
            lo2 |= (unsigned)l << (16 * q);
        }
        g_W1[p] = hi2;
        g_W2[p] = lo2;
    }
    if (idx < HSZ) g_bias[idx] = b_ih[idx] + b_hh[idx];
}

// B (state) SMEM layout: [buf 2][level hi/lo][n 8][k' 320] bf16, n-stride padded.
// k' order per CTA: [0,128) = local h, [128,192) = x, [192,320) = peer h.
#define NSTR 656              // bytes per n-row (320*2 padded; 164 words, 164%32=4 -> conflict-free frags)
#define LVL  (NB * NSTR)      // 5248 per level
#define BUFB (2 * LVL)        // 10496 per buffer

static __device__ __forceinline__ unsigned s2u(const void* p) {
    return (unsigned)__cvta_generic_to_shared(p);
}
static __device__ __forceinline__ unsigned lds32(unsigned ad) {
    unsigned v;
    asm volatile("ld.shared.u32 %0, [%1];" : "=r"(v) : "r"(ad));
    return v;
}
static __device__ __forceinline__ unsigned short lds16(unsigned ad) {
    unsigned short v;
    asm volatile("ld.shared.u16 %0, [%1];" : "=h"(v) : "r"(ad));
    return v;
}
static __device__ __forceinline__ void sts16(unsigned ad, unsigned short v) {
    asm volatile("st.shared.u16 [%0], %1;" :: "r"(ad), "h"(v) : "memory");
}
static __device__ __forceinline__ void sts32(unsigned ad, unsigned v) {
    asm volatile("st.shared.u32 [%0], %1;" :: "r"(ad), "r"(v) : "memory");
}
static __device__ __forceinline__ void sts16_cluster(unsigned ad, unsigned short v) {
    asm volatile("st.shared::cluster.u16 [%0], %1;" :: "r"(ad), "h"(v) : "memory");
}
static __device__ __forceinline__ void bar_arrive_remote(unsigned bar_remote) {
    asm volatile("mbarrier.arrive.release.cluster.shared::cluster.b64 _, [%0];" :: "r"(bar_remote) : "memory");
}
static __device__ __forceinline__ void bar_wait(unsigned bar, unsigned phase) {
    asm volatile("{\n\t.reg .pred P;\n\t"
                 "WLOOP_%=:\n\t"
                 "mbarrier.try_wait.parity.acquire.cluster.shared::cta.b64 P, [%0], %1, 0x989680;\n\t"
                 "@P bra.uni WDONE_%=;\n\t"
                 "bra.uni WLOOP_%=;\n\t"
                 "WDONE_%=:\n\t}"
                 :: "r"(bar), "r"(phase) : "memory");
}
static __device__ __forceinline__ unsigned mapa_u32(unsigned ad, int r) {
    unsigned q;
    asm("mapa.shared::cluster.u32 %0, %1, %2;" : "=r"(q) : "r"(ad), "r"(r));
    return q;
}
static __device__ __forceinline__ float tanh_fast(float v) {
    float e, r;
    asm("ex2.approx.f32 %0, %1;" : "=f"(e) : "f"(v * 2.885390082f));
    asm("rcp.approx.f32 %0, %1;" : "=f"(r) : "f"(e + 1.0f));
    return 1.0f - 2.0f * r;
}
static __device__ __forceinline__ void bsplit(float v, unsigned short& h, unsigned short& l) {
    h = __bfloat16_as_ushort(__float2bfloat16(v));
    float r = v - __bfloat162float(__ushort_as_bfloat16(h));
    l = __bfloat16_as_ushort(__float2bfloat16(r));
}
static __device__ __forceinline__ void mma_bf16(float* c, const unsigned* a, unsigned b0, unsigned b1) {
    asm volatile("mma.sync.aligned.m16n8k16.row.col.f32.bf16.bf16.f32 "
                 "{%0,%1,%2,%3}, {%4,%5,%6,%7}, {%8,%9}, {%0,%1,%2,%3};"
                 : "+f"(c[0]), "+f"(c[1]), "+f"(c[2]), "+f"(c[3])
                 : "r"(a[0]), "r"(a[1]), "r"(a[2]), "r"(a[3]), "r"(b0), "r"(b1));
}

__global__ void __cluster_dims__(2, 1, 1) __launch_bounds__(NTH, 1)
rnn_kernel(const float* __restrict__ x,
           const float* __restrict__ fc_W,
           const float* __restrict__ fc_b,
           float* __restrict__ out) {
    __shared__ __align__(16) unsigned char smB[2 * BUFB];   // 20992 B
    __shared__ __align__(16) float red[8][32][4];           // cross-kq partials
    __shared__ float fcred[64];
    __shared__ __align__(8) unsigned long long step_bar_s;

    cg::cluster_group cl = cg::this_cluster();
    const int rank = (int)cl.block_rank();
    const int tid  = threadIdx.x;
    const int lane = tid & 31;
    const int wid  = tid >> 5;
    const int peer = rank ^ 1;
    const int clus = blockIdx.x >> 1;
    const int mt   = wid & 7;      // m-tile (16 rows each)
    const int kq   = wid >> 3;     // k-half: 0 = k' 0..159 (local+x0), 1 = 160..319 (x1+peer)

    const unsigned Bu  = s2u(smB);
    const unsigned bar = s2u(&step_bar_s);

    // ---- A fragments (weights) -> registers, remapping global kp -> per-CTA k' order
    unsigned A1[10][4], A2[10][4];
    {
        const int jlo = rank * 128 + mt * 16 + (lane >> 2);
        #pragma unroll
        for (int s = 0; s < 10; ++s)
            #pragma unroll
            for (int e = 0; e < 4; ++e) {
                int j   = jlo + (e & 1) * 8;
                int kpp = kq * 80 + s * 8 + (e >> 1) * 4 + (lane & 3);   // k'-pair index
                int gkp = (kpp < 64) ? rank * 64 + kpp
                        : (kpp < 96) ? 64 + kpp                          // x pairs: 128 + (kpp-64)
                        :              peer * 64 + (kpp - 96);
                A1[s][e] = g_W1[j * KP + gkp];
                A2[s][e] = g_W2[j * KP + gkp];
            }
    }
    const float bias0 = g_bias[rank * 128 + mt * 16 + (lane >> 2)];
    const float bias1 = g_bias[rank * 128 + mt * 16 + (lane >> 2) + 8];

    // ---- zero both buffers, stage x(0)->buf0, x(1)->buf1
    for (int i = tid; i < (int)(2 * BUFB / 4); i += NTH)
        reinterpret_cast<unsigned*>(smB)[i] = 0u;
    __syncthreads();
    const float* xb = x + (size_t)(clus * NB) * TSTEPS * ISZ;
    {
        int n = tid >> 6, i = tid & 63;
        #pragma unroll
        for (int tt = 0; tt < 2; ++tt) {
            float v = xb[(size_t)n * TSTEPS * ISZ + (size_t)tt * ISZ + i];
            unsigned short h, l;
            bsplit(v, h, l);
            unsigned ad = Bu + tt * BUFB + n * NSTR + (128 + i) * 2;
            sts16(ad, h);
            sts16(ad + LVL, l);
        }
    }
    if (tid == 0)
        asm volatile("mbarrier.init.shared.b64 [%0], 1;" :: "r"(bar) : "memory");
    __syncthreads();
    asm volatile("barrier.cluster.arrive.aligned;" ::: "memory");
    asm volatile("barrier.cluster.wait.aligned;" ::: "memory");

    const unsigned peerBu  = mapa_u32(Bu, peer);
    const unsigned peerBar = mapa_u32(bar, peer);
    if (tid == 0) bar_arrive_remote(peerBar);   // bootstrap

    unsigned pS = 0;
    for (int t = 0; t < TSTEPS; ++t) {
        // prefetch x(t+2) (kq1 threads)
        float xv0 = 0.f, xv1 = 0.f;
        if (tid >= 256 && t + 2 < TSTEPS) {
            int v = (tid - 256) * 2, n = v >> 6, i = v & 63;
            const float* px = &xb[(size_t)n * TSTEPS * ISZ + (size_t)(t + 2) * ISZ + i];
            xv0 = px[0];
            xv1 = px[1];
        }
        const unsigned curB = Bu + (t & 1) * BUFB;

        if (kq) { bar_wait(bar, pS); }   // peer half needs peer's h(t)

        // ---- 30 HMMA over this warp's k-half, 3 accumulator sets
        float c0[4] = {0, 0, 0, 0}, c1[4] = {0, 0, 0, 0}, c2[4] = {0, 0, 0, 0};
        {
            unsigned badr = curB + (lane >> 2) * NSTR + (kq * 160 + (lane & 3) * 2) * 2;
            #pragma unroll
            for (int s = 0; s < 10; ++s) {
                unsigned ad  = badr + s * 32;
                unsigned bh0 = lds32(ad),        bh1 = lds32(ad + 16);
                unsigned bl0 = lds32(ad + LVL),  bl1 = lds32(ad + LVL + 16);
                mma_bf16(c0, A1[s], bh0, bh1);   // W-hi * s-hi
                mma_bf16(c1, A1[s], bl0, bl1);   // W-hi * s-lo
                mma_bf16(c2, A2[s], bh0, bh1);   // W-lo * s-hi
            }
        }

        if (kq) {
            float4* rp = reinterpret_cast<float4*>(&red[mt][lane][0]);
            *rp = make_float4(c0[0] + c1[0] + c2[0], c0[1] + c1[1] + c2[1],
                              c0[2] + c1[2] + c2[2], c0[3] + c1[3] + c2[3]);
        }
        __syncthreads();

        if (!kq) {
            // ---- reduce + bias + tanh + publish h(t+1) local & DSMEM
            float4 pr = *reinterpret_cast<float4*>(&red[mt][lane][0]);
            float d0 = c0[0] + c1[0] + c2[0] + pr.x + bias0;
            float d1 = c0[1] + c1[1] + c2[1] + pr.y + bias0;
            float d2 = c0[2] + c1[2] + c2[2] + pr.z + bias1;
            float d3 = c0[3] + c1[3] + c2[3] + pr.w + bias1;
            float h0 = tanh_fast(d0), h1 = tanh_fast(d1);
            float h2 = tanh_fast(d2), h3 = tanh_fast(d3);
            const int jl = mt * 16 + (lane >> 2);       // local k' (this CTA's row)
            const int n0 = (lane & 3) * 2;
            const unsigned nxt  = Bu + ((t + 1) & 1) * BUFB;
            const unsigned pnxt = peerBu + ((t + 1) & 1) * BUFB;
            unsigned short hh, hl;
            #pragma unroll
            for (int e = 0; e < 4; ++e) {
                float hv = (e == 0) ? h0 : (e == 1) ? h1 : (e == 2) ? h2 : h3;
                int jj = jl + (e >> 1) * 8;
                int nn = n0 + (e & 1);
                bsplit(hv, hh, hl);
                unsigned al = nxt + nn * NSTR + jj * 2;            // local k' = jj
                sts16(al, hh);
                sts16(al + LVL, hl);
                unsigned ar = pnxt + nn * NSTR + (192 + jj) * 2;   // peer sees us at 192+jj
                sts16_cluster(ar, hh);
                sts16_cluster(ar + LVL, hl);
            }
        } else if (t + 2 < TSTEPS) {
            // ---- stage x(t+2) into the buffer just freed (curB)
            int v = (tid - 256) * 2, n = v >> 6, i = v & 63;
            unsigned short h0, l0, h1, l1;
            bsplit(xv0, h0, l0);
            bsplit(xv1, h1, l1);
            unsigned ad = curB + n * NSTR + (128 + i) * 2;
            sts32(ad, (unsigned)h0 | ((unsigned)h1 << 16));
            sts32(ad + LVL, (unsigned)l0 | ((unsigned)l1 << 16));
        }
        __syncthreads();
        if (tid == 0) bar_arrive_remote(peerBar);
        pS ^= 1;
    }

    // peer's final pushes must land before rank0 reads the full state
    asm volatile("barrier.cluster.arrive.aligned;" ::: "memory");
    asm volatile("barrier.cluster.wait.aligned;" ::: "memory");

    // ---- final FC (O=1): h(512) is in buf0 (hi+lo reconstruct)
    if (rank == 0 && tid < 256) {
        int j  = tid;
        int kp = (j < 128) ? j : j + 64;   // peer rows at k' 192+(j-128)
        float fw = fc_W[j];
        float p[8];
        #pragma unroll
        for (int n = 0; n < 8; ++n) {
            unsigned ad = Bu + n * NSTR + kp * 2;
            float h = __bfloat162float(__ushort_as_bfloat16(lds16(ad))) +
                      __bfloat162float(__ushort_as_bfloat16(lds16(ad + LVL)));
            p[n] = h * fw;
        }
        #pragma unroll
        for (int off = 16; off; off >>= 1)
            #pragma unroll
            for (int n = 0; n < 8; ++n)
                p[n] += __shfl_down_sync(0xffffffffu, p[n], off);
        if (lane == 0)
            #pragma unroll
            for (int n = 0; n < 8; ++n) fcred[(tid >> 5) * 8 + n] = p[n];
    }
    __syncthreads();
    if (rank == 0 && tid < NB) {
        float s = fc_b[0];
        #pragma unroll
        for (int w = 0; w < 8; ++w) s += fcred[w * 8 + tid];
        out[clus * NB + tid] = s;
    }
    asm volatile("barrier.cluster.arrive.aligned;" ::: "memory");
    asm volatile("barrier.cluster.wait.aligned;" ::: "memory");
}

extern "C" void kernel_launch(void* const* d_in, const int* in_sizes, int n_in,
                              void* d_out, int out_size) {
    const float* x    = (const float*)d_in[0];
    const float* W_ih = (const float*)d_in[1];
    const float* W_hh = (const float*)d_in[2];
    const float* b_ih = (const float*)d_in[3];
    const float* b_hh = (const float*)d_in[4];
    const float* fc_W = (const float*)d_in[5];
    const float* fc_b = (const float*)d_in[6];
    float* out = (float*)d_out;

    prep_kernel<<<128, 256>>>(W_ih, W_hh, b_ih, b_hh);
    rnn_kernel<<<NBLOCKS, NTH>>>(x, fc_W, fc_b, out);
}

// round 15
// speedup vs baseline: 1.3097x; 1.0113x over previous
#include <cuda_runtime.h>
#include <cuda_bf16.h>
#include <cooperative_groups.h>
namespace cg = cooperative_groups;

#define TSTEPS 512
#define ISZ    64
#define HSZ    256
#define NB     8              // batch per cluster = MMA N
#define NTH    512
#define NBLOCKS 64            // 32 clusters x 2 CTAs
#define KP     160            // u32 bf16-pairs per weight row (K=320)

__device__ unsigned g_W1[HSZ * KP];   // bf16-hi pairs, [j][kp], global k order (h 0..255, x 256..319)
__device__ unsigned g_W2[HSZ * KP];   // bf16-lo pairs
__device__ float    g_bias[HSZ];

__global__ void prep_kernel(const float* __restrict__ W_ih,
                            const float* __restrict__ W_hh,
                            const float* __restrict__ b_ih,
                            const float* __restrict__ b_hh) {
    int idx = blockIdx.x * blockDim.x + threadIdx.x;
    int stride = gridDim.x * blockDim.x;
    for (int p = idx; p < HSZ * KP; p += stride) {
        int j = p / KP, kp = p % KP;
        unsigned hi2 = 0, lo2 = 0;
        #pragma unroll
        for (int q = 0; q < 2; ++q) {
            int k = 2 * kp + q;
            float w = (k < HSZ) ? W_hh[j * HSZ + k] : W_ih[j * ISZ + (k - HSZ)];
            unsigned short h = __bfloat16_as_ushort(__float2bfloat16(w));
            float r = w - __bfloat162float(__ushort_as_bfloat16(h));
            unsigned short l = __bfloat16_as_ushort(__float2bfloat16(r));
            hi2 |= (unsigned)h << (16 * q);
            lo2 |= (unsigned)l << (16 * q);
        }
        g_W1[p] = hi2;
        g_W2[p] = lo2;
    }
    if (idx < HSZ) g_bias[idx] = b_ih[idx] + b_hh[idx];
}

// B (state) SMEM layout: [buf 2][level hi/lo][n 8][k' 320] bf16, n-stride padded.
// k' order per CTA: [0,128) = local h, [128,192) = x, [192,320) = peer h.
#define NSTR 656              // bytes per n-row (320*2 padded)
#define LVL  (NB * NSTR)      // 5248 per level
#define BUFB (2 * LVL)        // 10496 per buffer

static __device__ __forceinline__ unsigned s2u(const void* p) {
    return (unsigned)__cvta_generic_to_shared(p);
}
static __device__ __forceinline__ unsigned lds32(unsigned ad) {
    unsigned v;
    asm volatile("ld.shared.u32 %0, [%1];" : "=r"(v) : "r"(ad));
    return v;
}
static __device__ __forceinline__ unsigned short lds16(unsigned ad) {
    unsigned short v;
    asm volatile("ld.shared.u16 %0, [%1];" : "=h"(v) : "r"(ad));
    return v;
}
static __device__ __forceinline__ void sts32(unsigned ad, unsigned v) {
    asm volatile("st.shared.u32 [%0], %1;" :: "r"(ad), "r"(v) : "memory");
}
static __device__ __forceinline__ void sts32_cluster(unsigned ad, unsigned v) {
    asm volatile("st.shared::cluster.u32 [%0], %1;" :: "r"(ad), "r"(v) : "memory");
}
static __device__ __forceinline__ void sts16(unsigned ad, unsigned short v) {
    asm volatile("st.shared.u16 [%0], %1;" :: "r"(ad), "h"(v) : "memory");
}
static __device__ __forceinline__ void bar_arrive_remote(unsigned bar_remote) {
    asm volatile("mbarrier.arrive.release.cluster.shared::cluster.b64 _, [%0];" :: "r"(bar_remote) : "memory");
}
static __device__ __forceinline__ void bar_wait(unsigned bar, unsigned phase) {
    asm volatile("{\n\t.reg .pred P;\n\t"
                 "WLOOP_%=:\n\t"
                 "mbarrier.try_wait.parity.acquire.cluster.shared::cta.b64 P, [%0], %1, 0x989680;\n\t"
                 "@P bra.uni WDONE_%=;\n\t"
                 "bra.uni WLOOP_%=;\n\t"
                 "WDONE_%=:\n\t}"
                 :: "r"(bar), "r"(phase) : "memory");
}
static __device__ __forceinline__ unsigned mapa_u32(unsigned ad, int r) {
    unsigned q;
    asm("mapa.shared::cluster.u32 %0, %1, %2;" : "=r"(q) : "r"(ad), "r"(r));
    return q;
}
static __device__ __forceinline__ float tanh_fast(float v) {
    float e, r;
    asm("ex2.approx.f32 %0, %1;" : "=f"(e) : "f"(v * 2.885390082f));
    asm("rcp.approx.f32 %0, %1;" : "=f"(r) : "f"(e + 1.0f));
    return 1.0f - 2.0f * r;
}
static __device__ __forceinline__ void bsplit(float v, unsigned& h, unsigned& l) {
    unsigned short hs = __bfloat16_as_ushort(__float2bfloat16(v));
    float r = v - __bfloat162float(__ushort_as_bfloat16(hs));
    h = hs;
    l = __bfloat16_as_ushort(__float2bfloat16(r));
}
static __device__ __forceinline__ void mma_bf16(float* c, const unsigned* a, unsigned b0, unsigned b1) {
    asm volatile("mma.sync.aligned.m16n8k16.row.col.f32.bf16.bf16.f32 "
                 "{%0,%1,%2,%3}, {%4,%5,%6,%7}, {%8,%9}, {%0,%1,%2,%3};"
                 : "+f"(c[0]), "+f"(c[1]), "+f"(c[2]), "+f"(c[3])
                 : "r"(a[0]), "r"(a[1]), "r"(a[2]), "r"(a[3]), "r"(b0), "r"(b1));
}

__global__ void __cluster_dims__(2, 1, 1) __launch_bounds__(NTH, 1)
rnn_kernel(const float* __restrict__ x,
           const float* __restrict__ fc_W,
           const float* __restrict__ fc_b,
           float* __restrict__ out) {
    __shared__ __align__(16) unsigned char smB[2 * BUFB];   // 20992 B
    __shared__ __align__(8) float2 red2x[2][8][32];         // cross-kq partial exchange
    __shared__ float fcred[64];
    __shared__ __align__(8) unsigned long long step_bar_s;

    cg::cluster_group cl = cg::this_cluster();
    const int rank = (int)cl.block_rank();
    const int tid  = threadIdx.x;
    const int lane = tid & 31;
    const int wid  = tid >> 5;
    const int peer = rank ^ 1;
    const int clus = blockIdx.x >> 1;
    const int mt   = wid & 7;      // m-tile (16 rows each)
    const int kq   = wid >> 3;     // k-half: 0 = k' 0..159, 1 = 160..319

    const unsigned Bu  = s2u(smB);
    const unsigned bar = s2u(&step_bar_s);

    // ---- A fragments (weights) -> registers, remapping global kp -> per-CTA k' order
    unsigned A1[10][4], A2[10][4];
    {
        const int jlo = rank * 128 + mt * 16 + (lane >> 2);
        #pragma unroll
        for (int s = 0; s < 10; ++s)
            #pragma unroll
            for (int e = 0; e < 4; ++e) {
                int j   = jlo + (e & 1) * 8;
                int kpp = kq * 80 + s * 8 + (e >> 1) * 4 + (lane & 3);   // k'-pair index
                int gkp = (kpp < 64) ? rank * 64 + kpp
                        : (kpp < 96) ? 64 + kpp                          // x pairs: 128 + (kpp-64)
                        :              peer * 64 + (kpp - 96);
                A1[s][e] = g_W1[j * KP + gkp];
                A2[s][e] = g_W2[j * KP + gkp];
            }
    }
    // this thread's epilogue row: kq0 -> rows [mt*16, +8), kq1 -> rows [mt*16+8, +8)
    const int erow = mt * 16 + kq * 8 + (lane >> 2);          // local row index 0..127
    const float biasE = g_bias[rank * 128 + erow];
    const int n0 = (lane & 3) * 2;                            // epilogue cols n0, n0+1

    // ---- zero both buffers, stage x(0)->buf0, x(1)->buf1
    for (int i = tid; i < (int)(2 * BUFB / 4); i += NTH)
        reinterpret_cast<unsigned*>(smB)[i] = 0u;
    __syncthreads();
    const float* xb = x + (size_t)(clus * NB) * TSTEPS * ISZ;
    {
        int n = tid >> 6, i = tid & 63;
        #pragma unroll
        for (int tt = 0; tt < 2; ++tt) {
            float v = xb[(size_t)n * TSTEPS * ISZ + (size_t)tt * ISZ + i];
            unsigned h, l;
            bsplit(v, h, l);
            unsigned ad = Bu + tt * BUFB + n * NSTR + (128 + i) * 2;
            sts16(ad, (unsigned short)h);
            sts16(ad + LVL, (unsigned short)l);
        }
    }
    if (tid == 0)
        asm volatile("mbarrier.init.shared.b64 [%0], 1;" :: "r"(bar) : "memory");
    __syncthreads();
    asm volatile("barrier.cluster.arrive.aligned;" ::: "memory");
    asm volatile("barrier.cluster.wait.aligned;" ::: "memory");

    const unsigned peerBu  = mapa_u32(Bu, peer);
    const unsigned peerBar = mapa_u32(bar, peer);
    if (tid == 0) bar_arrive_remote(peerBar);   // bootstrap

    unsigned pS = 0;
    for (int t = 0; t < TSTEPS; ++t) {
        // ---- prefetch + pre-split x(t+2) (kq1 threads), 2 regs held through GEMM
        unsigned xs_hi = 0, xs_lo = 0;
        if (kq && t + 2 < TSTEPS) {
            int v = (tid - 256) * 2, n = v >> 6, i = v & 63;
            const float* px = &xb[(size_t)n * TSTEPS * ISZ + (size_t)(t + 2) * ISZ + i];
            unsigned h0, l0, h1, l1;
            bsplit(px[0], h0, l0);
            bsplit(px[1], h1, l1);
            xs_hi = h0 | (h1 << 16);
            xs_lo = l0 | (l1 << 16);
        }
        const unsigned curB = Bu + (t & 1) * BUFB;

        if (kq) { bar_wait(bar, pS); }   // peer half needs peer's h(t)

        // ---- 30 HMMA over this warp's k-half, 3 accumulator sets
        float c0[4] = {0, 0, 0, 0}, c1[4] = {0, 0, 0, 0}, c2[4] = {0, 0, 0, 0};
        {
            unsigned badr = curB + (lane >> 2) * NSTR + (kq * 160 + (lane & 3) * 2) * 2;
            #pragma unroll
            for (int s = 0; s < 10; ++s) {
                unsigned ad  = badr + s * 32;
                unsigned bh0 = lds32(ad),        bh1 = lds32(ad + 16);
                unsigned bl0 = lds32(ad + LVL),  bl1 = lds32(ad + LVL + 16);
                mma_bf16(c0, A1[s], bh0, bh1);   // W-hi * s-hi
                mma_bf16(c1, A1[s], bl0, bl1);   // W-hi * s-lo
                mma_bf16(c2, A2[s], bh0, bh1);   // W-lo * s-hi
            }
        }
        float s0 = c0[0] + c1[0] + c2[0];
        float s1 = c0[1] + c1[1] + c2[1];
        float s2 = c0[2] + c1[2] + c2[2];
        float s3 = c0[3] + c1[3] + c2[3];

        // ---- exchange the partials each side does NOT finish
        // kq0 finishes e=0,1 (rows mt*16+q); kq1 finishes e=2,3 (rows mt*16+8+q)
        red2x[kq][mt][lane] = kq ? make_float2(s0, s1) : make_float2(s2, s3);
        asm volatile("bar.sync %0, 64;" :: "r"(mt + 1) : "memory");
        float2 pr = red2x[kq ^ 1][mt][lane];
        float d0 = (kq ? s2 : s0) + pr.x + biasE;
        float d1 = (kq ? s3 : s1) + pr.y + biasE;

        // ---- tanh + split + paired-row u32 publish (local from even-row lanes, remote from odd)
        {
            unsigned hh0, hl0, hh1, hl1;
            bsplit(tanh_fast(d0), hh0, hl0);   // col n0
            bsplit(tanh_fast(d1), hh1, hl1);   // col n0+1
            unsigned o_hh0 = __shfl_xor_sync(0xffffffffu, hh0, 4);
            unsigned o_hl0 = __shfl_xor_sync(0xffffffffu, hl0, 4);
            unsigned o_hh1 = __shfl_xor_sync(0xffffffffu, hh1, 4);
            unsigned o_hl1 = __shfl_xor_sync(0xffffffffu, hl1, 4);
            const int jj = erow & ~1;                       // even row of the pair
            if ((lane & 4) == 0) {                          // even row: local stores
                unsigned nxt = Bu + ((t + 1) & 1) * BUFB;
                unsigned a0 = nxt + n0 * NSTR + jj * 2;
                unsigned a1 = a0 + NSTR;
                sts32(a0,       hh0 | (o_hh0 << 16));
                sts32(a0 + LVL, hl0 | (o_hl0 << 16));
                sts32(a1,       hh1 | (o_hh1 << 16));
                sts32(a1 + LVL, hl1 | (o_hl1 << 16));
            } else {                                        // odd row: remote stores
                unsigned pnxt = peerBu + ((t + 1) & 1) * BUFB;
                unsigned a0 = pnxt + n0 * NSTR + (192 + jj) * 2;
                unsigned a1 = a0 + NSTR;
                sts32_cluster(a0,       o_hh0 | (hh0 << 16));
                sts32_cluster(a0 + LVL, o_hl0 | (hl0 << 16));
                sts32_cluster(a1,       o_hh1 | (hh1 << 16));
                sts32_cluster(a1 + LVL, o_hl1 | (hl1 << 16));
            }
        }

        // ---- stage x(t+2) into the buffer just freed (curB)
        if (kq && t + 2 < TSTEPS) {
            int v = (tid - 256) * 2, n = v >> 6, i = v & 63;
            unsigned ad = curB + n * NSTR + (128 + i) * 2;
            sts32(ad, xs_hi);
            sts32(ad + LVL, xs_lo);
        }
        __syncthreads();
        if (tid == 0) bar_arrive_remote(peerBar);
        pS ^= 1;
    }

    // peer's final pushes must land before rank0 reads the full state
    asm volatile("barrier.cluster.arrive.aligned;" ::: "memory");
    asm volatile("barrier.cluster.wait.aligned;" ::: "memory");

    // ---- final FC (O=1): h(512) is in buf0 (hi+lo reconstruct)
    if (rank == 0 && tid < 256) {
        int j  = tid;
        int kp = (j < 128) ? j : j + 64;   // peer rows at k' 192+(j-128)
        float fw = fc_W[j];
        float p[8];
        #pragma unroll
        for (int n = 0; n < 8; ++n) {
            unsigned ad = Bu + n * NSTR + kp * 2;
            float h = __bfloat162float(__ushort_as_bfloat16(lds16(ad))) +
                      __bfloat162float(__ushort_as_bfloat16(lds16(ad + LVL)));
            p[n] = h * fw;
        }
        #pragma unroll
        for (int off = 16; off; off >>= 1)
            #pragma unroll
            for (int n = 0; n < 8; ++n)
                p[n] += __shfl_down_sync(0xffffffffu, p[n], off);
        if (lane == 0)
            #pragma unroll
            for (int n = 0; n < 8; ++n) fcred[(tid >> 5) * 8 + n] = p[n];
    }
    __syncthreads();
    if (rank == 0 && tid < NB) {
        float s = fc_b[0];
        #pragma unroll
        for (int w = 0; w < 8; ++w) s += fcred[w * 8 + tid];
        out[clus * NB + tid] = s;
    }
    asm volatile("barrier.cluster.arrive.aligned;" ::: "memory");
    asm volatile("barrier.cluster.wait.aligned;" ::: "memory");
}

extern "C" void kernel_launch(void* const* d_in, const int* in_sizes, int n_in,
                              void* d_out, int out_size) {
    const float* x    = (const float*)d_in[0];
    const float* W_ih = (const float*)d_in[1];
    const float* W_hh = (const float*)d_in[2];
    const float* b_ih = (const float*)d_in[3];
    const float* b_hh = (const float*)d_in[4];
    const float* fc_W = (const float*)d_in[5];
    const float* fc_b = (const float*)d_in[6];
    float* out = (float*)d_out;

    prep_kernel<<<128, 256>>>(W_ih, W_hh, b_ih, b_hh);
    rnn_kernel<<<NBLOCKS, NTH>>>(x, fc_W, fc_b, out);
}

// round 17
// speedup vs baseline: 1.3580x; 1.0369x over previous
#include <cuda_runtime.h>
#include <cuda_bf16.h>
#include <cooperative_groups.h>
namespace cg = cooperative_groups;

#define TSTEPS 512
#define ISZ    64
#define HSZ    256
#define NB     8              // batch per cluster = MMA N
#define NTH    512
#define NBLOCKS 64            // 32 clusters x 2 CTAs
#define KP     160            // u32 bf16-pairs per weight row (global K=320: h pairs 0..127, x pairs 128..159)

__device__ unsigned g_W1[HSZ * KP];   // bf16-hi pairs
__device__ unsigned g_W2[HSZ * KP];   // bf16-lo pairs
__device__ float    g_bias[HSZ];
__device__ float    g_xw[32u * 512u * 256u * 8u];   // [clus][t][j][n] precomputed x-projection, 128MB

__global__ void prep_kernel(const float* __restrict__ W_ih,
                            const float* __restrict__ W_hh,
                            const float* __restrict__ b_ih,
                            const float* __restrict__ b_hh) {
    int idx = blockIdx.x * blockDim.x + threadIdx.x;
    int stride = gridDim.x * blockDim.x;
    for (int p = idx; p < HSZ * KP; p += stride) {
        int j = p / KP, kp = p % KP;
        unsigned hi2 = 0, lo2 = 0;
        #pragma unroll
        for (int q = 0; q < 2; ++q) {
            int k = 2 * kp + q;
            float w = (k < HSZ) ? W_hh[j * HSZ + k] : W_ih[j * ISZ + (k - HSZ)];
            unsigned short h = __bfloat16_as_ushort(__float2bfloat16(w));
            float r = w - __bfloat162float(__ushort_as_bfloat16(h));
            unsigned short l = __bfloat16_as_ushort(__float2bfloat16(r));
            hi2 |= (unsigned)h << (16 * q);
            lo2 |= (unsigned)l << (16 * q);
        }
        g_W1[p] = hi2;
        g_W2[p] = lo2;
    }
    if (idx < HSZ) g_bias[idx] = b_ih[idx] + b_hh[idx];
}

static __device__ __forceinline__ unsigned s2u(const void* p) {
    return (unsigned)__cvta_generic_to_shared(p);
}
static __device__ __forceinline__ unsigned lds32(unsigned ad) {
    unsigned v;
    asm volatile("ld.shared.u32 %0, [%1];" : "=r"(v) : "r"(ad));
    return v;
}
static __device__ __forceinline__ unsigned short lds16(unsigned ad) {
    unsigned short v;
    asm volatile("ld.shared.u16 %0, [%1];" : "=h"(v) : "r"(ad));
    return v;
}
static __device__ __forceinline__ void sts32(unsigned ad, unsigned v) {
    asm volatile("st.shared.u32 [%0], %1;" :: "r"(ad), "r"(v) : "memory");
}
static __device__ __forceinline__ void sts32_cluster(unsigned ad, unsigned v) {
    asm volatile("st.shared::cluster.u32 [%0], %1;" :: "r"(ad), "r"(v) : "memory");
}
static __device__ __forceinline__ void sts16(unsigned ad, unsigned short v) {
    asm volatile("st.shared.u16 [%0], %1;" :: "r"(ad), "h"(v) : "memory");
}
static __device__ __forceinline__ void bar_arrive_remote(unsigned bar_remote) {
    asm volatile("mbarrier.arrive.release.cluster.shared::cluster.b64 _, [%0];" :: "r"(bar_remote) : "memory");
}
static __device__ __forceinline__ void bar_wait(unsigned bar, unsigned phase) {
    asm volatile("{\n\t.reg .pred P;\n\t"
                 "WLOOP_%=:\n\t"
                 "mbarrier.try_wait.parity.acquire.cluster.shared::cta.b64 P, [%0], %1, 0x989680;\n\t"
                 "@P bra.uni WDONE_%=;\n\t"
                 "bra.uni WLOOP_%=;\n\t"
                 "WDONE_%=:\n\t}"
                 :: "r"(bar), "r"(phase) : "memory");
}
static __device__ __forceinline__ unsigned mapa_u32(unsigned ad, int r) {
    unsigned q;
    asm("mapa.shared::cluster.u32 %0, %1, %2;" : "=r"(q) : "r"(ad), "r"(r));
    return q;
}
static __device__ __forceinline__ float tanh_fast(float v) {
    float e, r;
    asm("ex2.approx.f32 %0, %1;" : "=f"(e) : "f"(v * 2.885390082f));
    asm("rcp.approx.f32 %0, %1;" : "=f"(r) : "f"(e + 1.0f));
    return 1.0f - 2.0f * r;
}
static __device__ __forceinline__ void bsplit(float v, unsigned& h, unsigned& l) {
    unsigned short hs = __bfloat16_as_ushort(__float2bfloat16(v));
    float r = v - __bfloat162float(__ushort_as_bfloat16(hs));
    h = hs;
    l = __bfloat16_as_ushort(__float2bfloat16(r));
}
static __device__ __forceinline__ void mma_bf16(float* c, const unsigned* a, unsigned b0, unsigned b1) {
    asm volatile("mma.sync.aligned.m16n8k16.row.col.f32.bf16.bf16.f32 "
                 "{%0,%1,%2,%3}, {%4,%5,%6,%7}, {%8,%9}, {%0,%1,%2,%3};"
                 : "+f"(c[0]), "+f"(c[1]), "+f"(c[2]), "+f"(c[3])
                 : "r"(a[0]), "r"(a[1]), "r"(a[2]), "r"(a[3]), "r"(b0), "r"(b1));
}

// ============================================================================
// Pre-pass: g_xw[clus][t][j][n] = sum_i x[clus*8+n][t][i] * W_ih[j][i]
// bf16x3 HMMA; grid (32 tblk, 32 clus), 256 threads.
// ============================================================================
#define PXSTR 144    // bytes per x-col row (36 words; 36 mod 32 = 4 -> conflict-free frags)
#define PXLVL (128 * PXSTR)   // 18432 per level

__global__ void __launch_bounds__(256, 1) prepass_kernel(const float* __restrict__ x) {
    __shared__ unsigned char Bx[2 * PXLVL];   // 36864 B
    const int tid  = threadIdx.x;
    const int lane = tid & 31;
    const int w    = tid >> 5;           // 8 warps
    const int tblk = blockIdx.x;         // 32 blocks of 16 t
    const int clus = blockIdx.y;         // 32

    const unsigned Bu = s2u(Bx);

    // ---- load + split x tile: 128 cols (tl*8+n) x 64 i
    for (int v = tid; v < 128 * ISZ; v += 256) {
        int col = v >> 6, i = v & 63;
        int tl = col >> 3, n = col & 7;
        int b = clus * 8 + n, t = tblk * 16 + tl;
        float f = x[((size_t)b * TSTEPS + t) * ISZ + i];
        unsigned h, l;
        bsplit(f, h, l);
        unsigned ad = Bu + col * PXSTR + i * 2;
        sts16(ad, (unsigned short)h);
        sts16(ad + PXLVL, (unsigned short)l);
    }

    // ---- A frags: x-part of W (pairs 128..159), 2 m-tiles per warp, 4 ksteps
    unsigned A1[2][4][4], A2[2][4][4];
    #pragma unroll
    for (int m = 0; m < 2; ++m) {
        int jlo = (w * 2 + m) * 16 + (lane >> 2);
        #pragma unroll
        for (int s = 0; s < 4; ++s)
            #pragma unroll
            for (int e = 0; e < 4; ++e) {
                int j = jlo + (e & 1) * 8;
                int kp = 128 + s * 8 + (e >> 1) * 4 + (lane & 3);
                A1[m][s][e] = g_W1[j * KP + kp];
                A2[m][s][e] = g_W2[j * KP + kp];
            }
    }
    __syncthreads();

    // ---- GEMM: 16 n-frags (= 16 t), accumulate 3 passes
    for (int nf = 0; nf < 16; ++nf) {
        float c[2][4] = {{0, 0, 0, 0}, {0, 0, 0, 0}};
        unsigned base = Bu + (nf * 8 + (lane >> 2)) * PXSTR + (lane & 3) * 4;
        #pragma unroll
        for (int s = 0; s < 4; ++s) {
            unsigned ad = base + s * 32;
            unsigned bh0 = lds32(ad),         bh1 = lds32(ad + 16);
            unsigned bl0 = lds32(ad + PXLVL), bl1 = lds32(ad + PXLVL + 16);
            #pragma unroll
            for (int m = 0; m < 2; ++m) {
                mma_bf16(c[m], A1[m][s], bh0, bh1);
                mma_bf16(c[m], A1[m][s], bl0, bl1);
                mma_bf16(c[m], A2[m][s], bh0, bh1);
            }
        }
        int t = tblk * 16 + nf;
        #pragma unroll
        for (int m = 0; m < 2; ++m) {
            int j = (w * 2 + m) * 16 + (lane >> 2);
            size_t idx = (((size_t)clus * TSTEPS + t) * HSZ + j) * 8 + (lane & 3) * 2;
            *reinterpret_cast<float2*>(&g_xw[idx])            = make_float2(c[m][0], c[m][1]);
            *reinterpret_cast<float2*>(&g_xw[idx + 8 * 8])    = make_float2(c[m][2], c[m][3]);
        }
    }
}

// ============================================================================
// Hot recurrence kernel: K=256 (h only), x-projection streamed from g_xw
// ============================================================================
// B (state) SMEM: [buf 2][level hi/lo][n 8][k' 256] bf16; n-stride 528 B
// k' per CTA: [0,128) = local h rows, [128,256) = peer h rows.
#define NSTR 528              // 132 words; 132 mod 32 = 4 -> conflict-free frag loads
#define LVL  (NB * NSTR)      // 4224
#define BUFB (2 * LVL)        // 8448

__global__ void __cluster_dims__(2, 1, 1) __launch_bounds__(NTH, 1)
rnn_kernel(const float* __restrict__ fc_W,
           const float* __restrict__ fc_b,
           float* __restrict__ out) {
    __shared__ __align__(16) unsigned char smB[2 * BUFB];   // 16896 B
    __shared__ __align__(8) float2 red2x[2][8][32];
    __shared__ float fcred[64];
    __shared__ __align__(8) unsigned long long step_bar_s;

    cg::cluster_group cl = cg::this_cluster();
    const int rank = (int)cl.block_rank();
    const int tid  = threadIdx.x;
    const int lane = tid & 31;
    const int wid  = tid >> 5;
    const int peer = rank ^ 1;
    const int clus = blockIdx.x >> 1;
    const int mt   = wid & 7;      // m-tile
    const int kq   = wid >> 3;     // k-half: 0 = local h (k' 0..127), 1 = peer h (128..255)

    const unsigned Bu  = s2u(smB);
    const unsigned bar = s2u(&step_bar_s);

    // ---- A fragments: 8 ksteps, 64+64 regs total for hi/lo
    unsigned A1[8][4], A2[8][4];
    {
        const int jlo = rank * 128 + mt * 16 + (lane >> 2);
        const int src = kq ? peer : rank;      // which CTA's rows this k-half covers
        #pragma unroll
        for (int s = 0; s < 8; ++s)
            #pragma unroll
            for (int e = 0; e < 4; ++e) {
                int j   = jlo + (e & 1) * 8;
                int gkp = src * 64 + s * 8 + (e >> 1) * 4 + (lane & 3);
                A1[s][e] = g_W1[j * KP + gkp];
                A2[s][e] = g_W2[j * KP + gkp];
            }
    }
    const int erow = mt * 16 + kq * 8 + (lane >> 2);   // epilogue row (local index)
    const float biasE = g_bias[rank * 128 + erow];
    const int n0 = (lane & 3) * 2;
    // per-step xw source for this thread's epilogue slots
    const float* xwp = g_xw + (((size_t)clus * TSTEPS) * HSZ + rank * 128 + erow) * 8 + n0;

    // ---- zero both state buffers (h(0) = 0; no x in state)
    for (int i = tid; i < (int)(2 * BUFB / 4); i += NTH)
        reinterpret_cast<unsigned*>(smB)[i] = 0u;
    if (tid == 0)
        asm volatile("mbarrier.init.shared.b64 [%0], 1;" :: "r"(bar) : "memory");
    __syncthreads();
    asm volatile("barrier.cluster.arrive.aligned;" ::: "memory");
    asm volatile("barrier.cluster.wait.aligned;" ::: "memory");

    const unsigned peerBu  = mapa_u32(Bu, peer);
    const unsigned peerBar = mapa_u32(bar, peer);
    if (tid == 0) bar_arrive_remote(peerBar);   // bootstrap

    unsigned pS = 0;
    for (int t = 0; t < TSTEPS; ++t) {
        // ---- prefetch this step's xw epilogue values (LDG hides under GEMM)
        float2 xwv = *reinterpret_cast<const float2*>(xwp + (size_t)t * (HSZ * 8));

        const unsigned curB = Bu + (t & 1) * BUFB;

        if (kq) { bar_wait(bar, pS); }   // peer half needs peer's h(t)

        // ---- 24 HMMA over this warp's k-half, 3 accumulator sets
        float c0[4] = {0, 0, 0, 0}, c1[4] = {0, 0, 0, 0}, c2[4] = {0, 0, 0, 0};
        {
            unsigned badr = curB + (lane >> 2) * NSTR + (kq * 128 + (lane & 3) * 2) * 2;
            #pragma unroll
            for (int s = 0; s < 8; ++s) {
                unsigned ad  = badr + s * 32;
                unsigned bh0 = lds32(ad),        bh1 = lds32(ad + 16);
                unsigned bl0 = lds32(ad + LVL),  bl1 = lds32(ad + LVL + 16);
                mma_bf16(c0, A1[s], bh0, bh1);   // W-hi * s-hi
                mma_bf16(c1, A1[s], bl0, bl1);   // W-hi * s-lo
                mma_bf16(c2, A2[s], bh0, bh1);   // W-lo * s-hi
            }
        }
        float s0 = c0[0] + c1[0] + c2[0];
        float s1 = c0[1] + c1[1] + c2[1];
        float s2 = c0[2] + c1[2] + c2[2];
        float s3 = c0[3] + c1[3] + c2[3];

        // ---- exchange the partials each side does NOT finish
        red2x[kq][mt][lane] = kq ? make_float2(s0, s1) : make_float2(s2, s3);
        asm volatile("bar.sync %0, 64;" :: "r"(mt + 1) : "memory");
        float2 pr = red2x[kq ^ 1][mt][lane];
        float d0 = (kq ? s2 : s0) + pr.x + biasE + xwv.x;
        float d1 = (kq ? s3 : s1) + pr.y + biasE + xwv.y;

        // ---- tanh + split + paired-row u32 publish (even-row lanes local, odd remote)
        {
            unsigned hh0, hl0, hh1, hl1;
            bsplit(tanh_fast(d0), hh0, hl0);   // col n0
            bsplit(tanh_fast(d1), hh1, hl1);   // col n0+1
            unsigned o_hh0 = __shfl_xor_sync(0xffffffffu, hh0, 4);
            unsigned o_hl0 = __shfl_xor_sync(0xffffffffu, hl0, 4);
            unsigned o_hh1 = __shfl_xor_sync(0xffffffffu, hh1, 4);
            unsigned o_hl1 = __shfl_xor_sync(0xffffffffu, hl1, 4);
            const int jj = erow & ~1;
            if ((lane & 4) == 0) {                          // even row: local stores (k' = jj)
                unsigned nxt = Bu + ((t + 1) & 1) * BUFB;
                unsigned a0 = nxt + n0 * NSTR + jj * 2;
                unsigned a1 = a0 + NSTR;
                sts32(a0,       hh0 | (o_hh0 << 16));
                sts32(a0 + LVL, hl0 | (o_hl0 << 16));
                sts32(a1,       hh1 | (o_hh1 << 16));
                sts32(a1 + LVL, hl1 | (o_hl1 << 16));
            } else {                                        // odd row: remote stores (k' = 128+jj)
                unsigned pnxt = peerBu + ((t + 1) & 1) * BUFB;
                unsigned a0 = pnxt + n0 * NSTR + (128 + jj) * 2;
                unsigned a1 = a0 + NSTR;
                sts32_cluster(a0,       o_hh0 | (hh0 << 16));
                sts32_cluster(a0 + LVL, o_hl0 | (hl0 << 16));
                sts32_cluster(a1,       o_hh1 | (hh1 << 16));
                sts32_cluster(a1 + LVL, o_hl1 | (hl1 << 16));
            }
        }
        __syncthreads();
        if (tid == 0) bar_arrive_remote(peerBar);
        pS ^= 1;
    }

    // peer's final pushes must land before rank0 reads the full state
    asm volatile("barrier.cluster.arrive.aligned;" ::: "memory");
    asm volatile("barrier.cluster.wait.aligned;" ::: "memory");

    // ---- final FC (O=1): h(512) in buf0; k' = j directly
    if (rank == 0 && tid < 256) {
        int j = tid;
        float fw = fc_W[j];
        float p[8];
        #pragma unroll
        for (int n = 0; n < 8; ++n) {
            unsigned ad = Bu + n * NSTR + j * 2;
            float h = __bfloat162float(__ushort_as_bfloat16(lds16(ad))) +
                      __bfloat162float(__ushort_as_bfloat16(lds16(ad + LVL)));
            p[n] = h * fw;
        }
        #pragma unroll
        for (int off = 16; off; off >>= 1)
            #pragma unroll
            for (int n = 0; n < 8; ++n)
                p[n] += __shfl_down_sync(0xffffffffu, p[n], off);
        if (lane == 0)
            #pragma unroll
            for (int n = 0; n < 8; ++n) fcred[(tid >> 5) * 8 + n] = p[n];
    }
    __syncthreads();
    if (rank == 0 && tid < NB) {
        float s = fc_b[0];
        #pragma unroll
        for (int w = 0; w < 8; ++w) s += fcred[w * 8 + tid];
        out[clus * NB + tid] = s;
    }
    asm volatile("barrier.cluster.arrive.aligned;" ::: "memory");
    asm volatile("barrier.cluster.wait.aligned;" ::: "memory");
}

extern "C" void kernel_launch(void* const* d_in, const int* in_sizes, int n_in,
                              void* d_out, int out_size) {
    const float* x    = (const float*)d_in[0];
    const float* W_ih = (const float*)d_in[1];
    const float* W_hh = (const float*)d_in[2];
    const float* b_ih = (const float*)d_in[3];
    const float* b_hh = (const float*)d_in[4];
    const float* fc_W = (const float*)d_in[5];
    const float* fc_b = (const float*)d_in[6];
    float* out = (float*)d_out;

    prep_kernel<<<128, 256>>>(W_ih, W_hh, b_ih, b_hh);
    prepass_kernel<<<dim3(32, 32), 256>>>(x);
    rnn_kernel<<<NBLOCKS, NTH>>>(fc_W, fc_b, out);
}